// round 2
// baseline (speedup 1.0000x reference)
#include <cuda_runtime.h>

#define BB 2
#define TT 2048
#define CCH 1024
#define HH 16
#define DD 64
#define MTOK (BB*TT)          // 4096 tokens

// Scratch (allocation-free rule: __device__ globals)
__device__ float g_qk[MTOK*CCH];
__device__ float g_v [MTOK*CCH];
__device__ float g_y [MTOK*CCH];

// ---------------------------------------------------------------------------
// GEMM:  Cout[M,N] = A[M,K] @ W[N,K]^T + bias[N]
// 128x128 block tile, BK=8, 256 threads, 8x8 microtile per thread.
// ---------------------------------------------------------------------------
__global__ __launch_bounds__(256) void gemm_bias_kernel(
    const float* __restrict__ A, const float* __restrict__ W,
    const float* __restrict__ bias, float* __restrict__ Cout,
    int M, int N, int K)
{
    __shared__ float As[8][128];
    __shared__ float Ws[8][128];

    const int tid = threadIdx.x;
    const int tx = tid & 15;          // 0..15 -> N microtile
    const int ty = tid >> 4;          // 0..15 -> M microtile
    const int m0 = blockIdx.y * 128;
    const int n0 = blockIdx.x * 128;

    const int lrow = tid >> 1;        // 0..127
    const int lk   = (tid & 1) * 4;   // 0 or 4

    float acc[8][8];
#pragma unroll
    for (int i = 0; i < 8; i++)
#pragma unroll
        for (int j = 0; j < 8; j++) acc[i][j] = 0.f;

    const float* Aptr = A + (size_t)(m0 + lrow) * K + lk;
    const float* Wptr = W + (size_t)(n0 + lrow) * K + lk;

    for (int k0 = 0; k0 < K; k0 += 8) {
        float4 av = *(const float4*)(Aptr + k0);
        float4 wv = *(const float4*)(Wptr + k0);
        __syncthreads();
        As[lk+0][lrow]=av.x; As[lk+1][lrow]=av.y; As[lk+2][lrow]=av.z; As[lk+3][lrow]=av.w;
        Ws[lk+0][lrow]=wv.x; Ws[lk+1][lrow]=wv.y; Ws[lk+2][lrow]=wv.z; Ws[lk+3][lrow]=wv.w;
        __syncthreads();
#pragma unroll
        for (int k = 0; k < 8; k++) {
            float4 a0 = *(float4*)&As[k][ty*8];
            float4 a1 = *(float4*)&As[k][ty*8+4];
            float4 b0 = *(float4*)&Ws[k][tx*8];
            float4 b1 = *(float4*)&Ws[k][tx*8+4];
            float a[8] = {a0.x,a0.y,a0.z,a0.w,a1.x,a1.y,a1.z,a1.w};
            float b[8] = {b0.x,b0.y,b0.z,b0.w,b1.x,b1.y,b1.z,b1.w};
#pragma unroll
            for (int i = 0; i < 8; i++)
#pragma unroll
                for (int j = 0; j < 8; j++)
                    acc[i][j] += a[i]*b[j];
        }
    }

#pragma unroll
    for (int i = 0; i < 8; i++) {
        const int m = m0 + ty*8 + i;
#pragma unroll
        for (int j = 0; j < 8; j++) {
            const int n = n0 + tx*8 + j;
            Cout[(size_t)m * N + n] = acc[i][j] + bias[n];
        }
    }
}

// ---------------------------------------------------------------------------
// Flash attention with shared Q==K projection, causal, fp32.
// Block handles 64 query rows for one (b,h). 256 threads = 16x16,
// each thread owns a 4x4 S/P microtile and a 4(row)x4(dcol) O microtile.
// Smem: Qs (d-major), KP (K d-major, later P c-major), Vs (row-major).
// ---------------------------------------------------------------------------
#define STRD 68
#define ATTN_SMEM (3 * 64 * STRD * 4)

__global__ __launch_bounds__(256) void attn_kernel(
    const float* __restrict__ qk, const float* __restrict__ v,
    float* __restrict__ y)
{
    extern __shared__ float sm[];
    float* Qs = sm;                 // [64 d][STRD]  Qs[d*STRD + r]
    float* KP = sm + 64*STRD;       // K: [d][r]; later P: [c][r]
    float* Vs = sm + 2*64*STRD;     // V: [r][d]

    const int tid = threadIdx.x;
    const int tx = tid & 15;
    const int ty = tid >> 4;
    const int qi = blockIdx.x;              // query tile 0..31
    const int bh = blockIdx.y;              // 0..31
    const int b  = bh / HH, h = bh % HH;
    const int q0 = qi * 64;
    const size_t base = ((size_t)b * TT) * CCH + (size_t)h * DD;  // + t*C + d

    // Load Q tile, transposed to d-major
#pragma unroll
    for (int q = 0; q < 4; q++) {
        int f = tid + 256*q;                 // 0..1023
        int r = f >> 4;                      // row in tile
        int c4 = (f & 15) * 4;               // d offset
        float4 val = *(const float4*)&qk[base + (size_t)(q0 + r)*CCH + c4];
        Qs[(c4+0)*STRD + r] = val.x;
        Qs[(c4+1)*STRD + r] = val.y;
        Qs[(c4+2)*STRD + r] = val.z;
        Qs[(c4+3)*STRD + r] = val.w;
    }

    float o[4][4];
    float m[4], l[4];
#pragma unroll
    for (int i = 0; i < 4; i++) {
        m[i] = -1e30f; l[i] = 0.f;
#pragma unroll
        for (int j = 0; j < 4; j++) o[i][j] = 0.f;
    }

    for (int kv = 0; kv <= qi; kv++) {
        __syncthreads();    // previous-iter readers done (also covers Q fill)
        // Load K (transposed, d-major) and V (row-major)
#pragma unroll
        for (int q = 0; q < 4; q++) {
            int f = tid + 256*q;
            int r = f >> 4;
            int c4 = (f & 15) * 4;
            size_t g = base + (size_t)(kv*64 + r)*CCH + c4;
            float4 kvl = *(const float4*)&qk[g];     // shared Q/K projection
            KP[(c4+0)*STRD + r] = kvl.x;
            KP[(c4+1)*STRD + r] = kvl.y;
            KP[(c4+2)*STRD + r] = kvl.z;
            KP[(c4+3)*STRD + r] = kvl.w;
            *(float4*)&Vs[r*STRD + c4] = *(const float4*)&v[g];
        }
        __syncthreads();

        // S = Q @ K^T  (4x4 per thread)
        float s[4][4];
#pragma unroll
        for (int i = 0; i < 4; i++)
#pragma unroll
            for (int j = 0; j < 4; j++) s[i][j] = 0.f;

#pragma unroll 8
        for (int d = 0; d < 64; d++) {
            float4 aq = *(float4*)&Qs[d*STRD + ty*4];
            float4 bq = *(float4*)&KP[d*STRD + tx*4];
            float av[4] = {aq.x,aq.y,aq.z,aq.w};
            float bv[4] = {bq.x,bq.y,bq.z,bq.w};
#pragma unroll
            for (int i = 0; i < 4; i++)
#pragma unroll
                for (int j = 0; j < 4; j++)
                    s[i][j] += av[i]*bv[j];
        }

        const float scale = 0.125f;     // 1/sqrt(64)
        const bool diag = (kv == qi);
#pragma unroll
        for (int i = 0; i < 4; i++) {
            const int qrow = q0 + ty*4 + i;
#pragma unroll
            for (int j = 0; j < 4; j++) {
                const int kcol = kv*64 + tx*4 + j;
                float val = s[i][j] * scale;
                if (diag && kcol > qrow) val = -1e30f;
                s[i][j] = val;
            }
        }

        // Online softmax (row reductions over 16 tx lanes via shfl)
#pragma unroll
        for (int i = 0; i < 4; i++) {
            float mx = fmaxf(fmaxf(s[i][0], s[i][1]), fmaxf(s[i][2], s[i][3]));
#pragma unroll
            for (int off = 8; off >= 1; off >>= 1)
                mx = fmaxf(mx, __shfl_xor_sync(0xffffffffu, mx, off));
            float mnew = fmaxf(m[i], mx);
            float corr = __expf(m[i] - mnew);
            m[i] = mnew;
            l[i] *= corr;
#pragma unroll
            for (int j = 0; j < 4; j++) o[i][j] *= corr;
            float ps = 0.f;
#pragma unroll
            for (int j = 0; j < 4; j++) {
                float p = __expf(s[i][j] - mnew);
                s[i][j] = p;
                ps += p;
            }
#pragma unroll
            for (int off = 8; off >= 1; off >>= 1)
                ps += __shfl_xor_sync(0xffffffffu, ps, off);
            l[i] += ps;
        }

        __syncthreads();    // everyone done reading K from KP
        // Store P transposed (c-major) into KP
#pragma unroll
        for (int i = 0; i < 4; i++)
#pragma unroll
            for (int j = 0; j < 4; j++)
                KP[(tx*4+j)*STRD + ty*4 + i] = s[i][j];
        __syncthreads();

        // O += P @ V
#pragma unroll 8
        for (int c = 0; c < 64; c++) {
            float4 ap = *(float4*)&KP[c*STRD + ty*4];
            float4 bv4 = *(float4*)&Vs[c*STRD + tx*4];
            float av[4] = {ap.x,ap.y,ap.z,ap.w};
            float bv[4] = {bv4.x,bv4.y,bv4.z,bv4.w};
#pragma unroll
            for (int i = 0; i < 4; i++)
#pragma unroll
                for (int j = 0; j < 4; j++)
                    o[i][j] += av[i]*bv[j];
        }
    }

    // Normalize and write y in [B,T,C] layout (head h -> cols h*64..)
#pragma unroll
    for (int i = 0; i < 4; i++) {
        const float inv = 1.f / l[i];
        const int t = q0 + ty*4 + i;
#pragma unroll
        for (int j = 0; j < 4; j++)
            y[base + (size_t)t*CCH + tx*4 + j] = o[i][j] * inv;
    }
}

// ---------------------------------------------------------------------------
extern "C" void kernel_launch(void* const* d_in, const int* in_sizes, int n_in,
                              void* d_out, int out_size)
{
    const float* hs  = (const float*)d_in[0];
    const float* Wqk = (const float*)d_in[1];
    const float* bqk = (const float*)d_in[2];
    const float* Wv  = (const float*)d_in[3];
    const float* bv  = (const float*)d_in[4];
    const float* Wo  = (const float*)d_in[5];
    const float* bo  = (const float*)d_in[6];
    float* out = (float*)d_out;

    float *qk, *v, *y;
    cudaGetSymbolAddress((void**)&qk, g_qk);
    cudaGetSymbolAddress((void**)&v,  g_v);
    cudaGetSymbolAddress((void**)&y,  g_y);

    cudaFuncSetAttribute(attn_kernel,
                         cudaFuncAttributeMaxDynamicSharedMemorySize, ATTN_SMEM);

    dim3 ggrid(CCH/128, MTOK/128);   // (8, 32)
    gemm_bias_kernel<<<ggrid, 256>>>(hs, Wqk, bqk, qk, MTOK, CCH, CCH);
    gemm_bias_kernel<<<ggrid, 256>>>(hs, Wv,  bv,  v,  MTOK, CCH, CCH);

    attn_kernel<<<dim3(TT/64, BB*HH), 256, ATTN_SMEM>>>(qk, v, y);

    gemm_bias_kernel<<<ggrid, 256>>>(y, Wo, bo, out, MTOK, CCH, CCH);
}

// round 4
// speedup vs baseline: 1.4305x; 1.4305x over previous
#include <cuda_runtime.h>
#include <cuda_bf16.h>
#include <cstdint>

#define BB 2
#define TT 2048
#define CCH 1024
#define HH 16
#define DD 64
#define MTOK (BB*TT)          // 4096 tokens

// Scratch (allocation-free rule: __device__ globals)
__device__ float g_qk[MTOK*CCH];
__device__ float g_v [MTOK*CCH];
__device__ float g_y [MTOK*CCH];

// ===========================================================================
// bf16x3 split-precision tensor-core GEMM
//   Cout[M,N] = A[M,K] @ W[N,K]^T + bias[N],  M=4096, N=K=1024 (fixed)
// 128x128 CTA tile, BK=32, 256 threads (8 warps, 2x4 warp grid, 64x32/warp).
// fp32 operands split as hi=bf16(x), lo=bf16(x-hi); acc += hi*hi+hi*lo+lo*hi.
// ===========================================================================
#define GK   1024
#define SSTR 40                        // bf16 per smem row (32 + 8 pad)
#define GT   (128*SSTR)                // bf16 elements per sub-tile
#define GSTAGE (4*GT)                  // Ah,Al,Bh,Bl
#define GEMM_SMEM (2*GSTAGE*2)         // bytes (2 stages, bf16)

__device__ __forceinline__ void mma_bf16(float c[4],
    const unsigned int a[4], const unsigned int b[2])
{
    asm volatile(
        "mma.sync.aligned.m16n8k16.row.col.f32.bf16.bf16.f32 "
        "{%0,%1,%2,%3}, {%4,%5,%6,%7}, {%8,%9}, {%0,%1,%2,%3};"
        : "+f"(c[0]), "+f"(c[1]), "+f"(c[2]), "+f"(c[3])
        : "r"(a[0]), "r"(a[1]), "r"(a[2]), "r"(a[3]), "r"(b[0]), "r"(b[1]));
}

__device__ __forceinline__ void ldsm4(const __nv_bfloat16* base, int row0,
    int kc, int lane, unsigned int r[4])
{
    const __nv_bfloat16* p = base + (row0 + (lane & 15)) * SSTR
                                  + kc + ((lane >> 4) << 3);
    unsigned int addr = (unsigned int)__cvta_generic_to_shared(p);
    asm volatile("ldmatrix.sync.aligned.m8n8.x4.shared.b16 {%0,%1,%2,%3}, [%4];"
        : "=r"(r[0]), "=r"(r[1]), "=r"(r[2]), "=r"(r[3]) : "r"(addr));
}

__device__ __forceinline__ void ldsm2(const __nv_bfloat16* base, int row0,
    int kc, int lane, unsigned int r[2])
{
    const __nv_bfloat16* p = base + (row0 + (lane & 7)) * SSTR
                                  + kc + (((lane >> 3) & 1) << 3);
    unsigned int addr = (unsigned int)__cvta_generic_to_shared(p);
    asm volatile("ldmatrix.sync.aligned.m8n8.x2.shared.b16 {%0,%1}, [%2];"
        : "=r"(r[0]), "=r"(r[1]) : "r"(addr));
}

__global__ __launch_bounds__(256) void gemm_bf16x3_kernel(
    const float* __restrict__ A, const float* __restrict__ W,
    const float* __restrict__ bias, float* __restrict__ Cout)
{
    extern __shared__ __nv_bfloat16 smem[];

    const int tid  = threadIdx.x;
    const int wid  = tid >> 5;
    const int lane = tid & 31;
    const int g    = lane >> 2;          // 0..7
    const int t4   = lane & 3;           // 0..3
    const int m0   = blockIdx.y * 128;
    const int n0   = blockIdx.x * 128;
    const int wm   = (wid & 1) * 64;     // warp m offset in tile
    const int wn   = (wid >> 1) * 32;    // warp n offset in tile

    // global-load mapping: 32 rows x 32 fp32 per pass, 4 passes
    const int lr = tid >> 3;             // 0..31
    const int lc = (tid & 7) * 4;        // 0,4,..,28

    float acc[4][4][4];
#pragma unroll
    for (int i = 0; i < 4; i++)
#pragma unroll
        for (int j = 0; j < 4; j++)
#pragma unroll
            for (int r = 0; r < 4; r++) acc[i][j][r] = 0.f;

    auto g_load = [&](const float* P, int row0, int kk, float4 v[4]) {
#pragma unroll
        for (int p = 0; p < 4; p++)
            v[p] = *(const float4*)&P[(size_t)(row0 + p*32 + lr) * GK + kk + lc];
    };

    auto cvt_store = [&](__nv_bfloat16* dh, __nv_bfloat16* dl, const float4 v[4]) {
#pragma unroll
        for (int p = 0; p < 4; p++) {
            const int r = p*32 + lr;
            float f[4] = {v[p].x, v[p].y, v[p].z, v[p].w};
            __nv_bfloat16 h[4], l[4];
#pragma unroll
            for (int q = 0; q < 4; q++) {
                h[q] = __float2bfloat16_rn(f[q]);
                l[q] = __float2bfloat16_rn(f[q] - __bfloat162float(h[q]));
            }
            *(__nv_bfloat162*)&dh[r*SSTR + lc    ] = __nv_bfloat162(h[0], h[1]);
            *(__nv_bfloat162*)&dh[r*SSTR + lc + 2] = __nv_bfloat162(h[2], h[3]);
            *(__nv_bfloat162*)&dl[r*SSTR + lc    ] = __nv_bfloat162(l[0], l[1]);
            *(__nv_bfloat162*)&dl[r*SSTR + lc + 2] = __nv_bfloat162(l[2], l[3]);
        }
    };

    // prologue: stage 0
    {
        float4 ta[4], tb[4];
        g_load(A, m0, 0, ta);
        g_load(W, n0, 0, tb);
        cvt_store(smem,        smem +   GT, ta);
        cvt_store(smem + 2*GT, smem + 3*GT, tb);
    }
    __syncthreads();

    const int nk = GK / 32;
    float4 ra[4], rb[4];
    for (int kt = 0; kt < nk; kt++) {
        const int s = kt & 1;
        __nv_bfloat16* sAh = smem + s*GSTAGE;
        __nv_bfloat16* sAl = sAh + GT;
        __nv_bfloat16* sBh = sAh + 2*GT;
        __nv_bfloat16* sBl = sAh + 3*GT;

        const bool more = (kt + 1 < nk);
        if (more) {
            g_load(A, m0, (kt+1)*32, ra);
            g_load(W, n0, (kt+1)*32, rb);
        }

#pragma unroll
        for (int ks = 0; ks < 32; ks += 16) {
            unsigned int ah[4][4], al[4][4], bh[4][2], bl[4][2];
#pragma unroll
            for (int i = 0; i < 4; i++) {
                ldsm4(sAh, wm + i*16, ks, lane, ah[i]);
                ldsm4(sAl, wm + i*16, ks, lane, al[i]);
            }
#pragma unroll
            for (int j = 0; j < 4; j++) {
                ldsm2(sBh, wn + j*8, ks, lane, bh[j]);
                ldsm2(sBl, wn + j*8, ks, lane, bl[j]);
            }
#pragma unroll
            for (int i = 0; i < 4; i++)
#pragma unroll
                for (int j = 0; j < 4; j++) {
                    mma_bf16(acc[i][j], ah[i], bh[j]);
                    mma_bf16(acc[i][j], ah[i], bl[j]);
                    mma_bf16(acc[i][j], al[i], bh[j]);
                }
        }

        if (more) {
            const int s2 = s ^ 1;
            __nv_bfloat16* dAh = smem + s2*GSTAGE;
            cvt_store(dAh,        dAh +   GT, ra);
            cvt_store(dAh + 2*GT, dAh + 3*GT, rb);
        }
        __syncthreads();
    }

    // epilogue: + bias, fp32 out
#pragma unroll
    for (int i = 0; i < 4; i++)
#pragma unroll
        for (int j = 0; j < 4; j++) {
            const int r = m0 + wm + i*16 + g;
            const int c = n0 + wn + j*8 + t4*2;
            const float b0v = bias[c], b1v = bias[c+1];
            float2 v0 = {acc[i][j][0] + b0v, acc[i][j][1] + b1v};
            float2 v1 = {acc[i][j][2] + b0v, acc[i][j][3] + b1v};
            *(float2*)&Cout[(size_t)r       * CCH + c] = v0;
            *(float2*)&Cout[(size_t)(r + 8) * CCH + c] = v1;
        }
}

// ---------------------------------------------------------------------------
// Flash attention with shared Q==K projection, causal, fp32 (unchanged R2).
// ---------------------------------------------------------------------------
#define STRD 68
#define ATTN_SMEM (3 * 64 * STRD * 4)

__global__ __launch_bounds__(256) void attn_kernel(
    const float* __restrict__ qk, const float* __restrict__ v,
    float* __restrict__ y)
{
    extern __shared__ float sm[];
    float* Qs = sm;                 // [64 d][STRD]  Qs[d*STRD + r]
    float* KP = sm + 64*STRD;       // K: [d][r]; later P: [c][r]
    float* Vs = sm + 2*64*STRD;     // V: [r][d]

    const int tid = threadIdx.x;
    const int tx = tid & 15;
    const int ty = tid >> 4;
    const int qi = blockIdx.x;
    const int bh = blockIdx.y;
    const int b  = bh / HH, h = bh % HH;
    const int q0 = qi * 64;
    const size_t base = ((size_t)b * TT) * CCH + (size_t)h * DD;

#pragma unroll
    for (int q = 0; q < 4; q++) {
        int f = tid + 256*q;
        int r = f >> 4;
        int c4 = (f & 15) * 4;
        float4 val = *(const float4*)&qk[base + (size_t)(q0 + r)*CCH + c4];
        Qs[(c4+0)*STRD + r] = val.x;
        Qs[(c4+1)*STRD + r] = val.y;
        Qs[(c4+2)*STRD + r] = val.z;
        Qs[(c4+3)*STRD + r] = val.w;
    }

    float o[4][4];
    float m[4], l[4];
#pragma unroll
    for (int i = 0; i < 4; i++) {
        m[i] = -1e30f; l[i] = 0.f;
#pragma unroll
        for (int j = 0; j < 4; j++) o[i][j] = 0.f;
    }

    for (int kv = 0; kv <= qi; kv++) {
        __syncthreads();
#pragma unroll
        for (int q = 0; q < 4; q++) {
            int f = tid + 256*q;
            int r = f >> 4;
            int c4 = (f & 15) * 4;
            size_t gg = base + (size_t)(kv*64 + r)*CCH + c4;
            float4 kvl = *(const float4*)&qk[gg];
            KP[(c4+0)*STRD + r] = kvl.x;
            KP[(c4+1)*STRD + r] = kvl.y;
            KP[(c4+2)*STRD + r] = kvl.z;
            KP[(c4+3)*STRD + r] = kvl.w;
            *(float4*)&Vs[r*STRD + c4] = *(const float4*)&v[gg];
        }
        __syncthreads();

        float s[4][4];
#pragma unroll
        for (int i = 0; i < 4; i++)
#pragma unroll
            for (int j = 0; j < 4; j++) s[i][j] = 0.f;

#pragma unroll 8
        for (int d = 0; d < 64; d++) {
            float4 aq = *(float4*)&Qs[d*STRD + ty*4];
            float4 bq = *(float4*)&KP[d*STRD + tx*4];
            float av[4] = {aq.x,aq.y,aq.z,aq.w};
            float bv[4] = {bq.x,bq.y,bq.z,bq.w};
#pragma unroll
            for (int i = 0; i < 4; i++)
#pragma unroll
                for (int j = 0; j < 4; j++)
                    s[i][j] += av[i]*bv[j];
        }

        const float scale = 0.125f;
        const bool diag = (kv == qi);
#pragma unroll
        for (int i = 0; i < 4; i++) {
            const int qrow = q0 + ty*4 + i;
#pragma unroll
            for (int j = 0; j < 4; j++) {
                const int kcol = kv*64 + tx*4 + j;
                float val = s[i][j] * scale;
                if (diag && kcol > qrow) val = -1e30f;
                s[i][j] = val;
            }
        }

#pragma unroll
        for (int i = 0; i < 4; i++) {
            float mx = fmaxf(fmaxf(s[i][0], s[i][1]), fmaxf(s[i][2], s[i][3]));
#pragma unroll
            for (int off = 8; off >= 1; off >>= 1)
                mx = fmaxf(mx, __shfl_xor_sync(0xffffffffu, mx, off));
            float mnew = fmaxf(m[i], mx);
            float corr = __expf(m[i] - mnew);
            m[i] = mnew;
            l[i] *= corr;
#pragma unroll
            for (int j = 0; j < 4; j++) o[i][j] *= corr;
            float ps = 0.f;
#pragma unroll
            for (int j = 0; j < 4; j++) {
                float p = __expf(s[i][j] - mnew);
                s[i][j] = p;
                ps += p;
            }
#pragma unroll
            for (int off = 8; off >= 1; off >>= 1)
                ps += __shfl_xor_sync(0xffffffffu, ps, off);
            l[i] += ps;
        }

        __syncthreads();
#pragma unroll
        for (int i = 0; i < 4; i++)
#pragma unroll
            for (int j = 0; j < 4; j++)
                KP[(tx*4+j)*STRD + ty*4 + i] = s[i][j];
        __syncthreads();

#pragma unroll 8
        for (int c = 0; c < 64; c++) {
            float4 ap = *(float4*)&KP[c*STRD + ty*4];
            float4 bv4 = *(float4*)&Vs[c*STRD + tx*4];
            float av[4] = {ap.x,ap.y,ap.z,ap.w};
            float bv[4] = {bv4.x,bv4.y,bv4.z,bv4.w};
#pragma unroll
            for (int i = 0; i < 4; i++)
#pragma unroll
                for (int j = 0; j < 4; j++)
                    o[i][j] += av[i]*bv[j];
        }
    }

#pragma unroll
    for (int i = 0; i < 4; i++) {
        const float inv = 1.f / l[i];
        const int t = q0 + ty*4 + i;
#pragma unroll
        for (int j = 0; j < 4; j++)
            y[base + (size_t)t*CCH + tx*4 + j] = o[i][j] * inv;
    }
}

// ---------------------------------------------------------------------------
extern "C" void kernel_launch(void* const* d_in, const int* in_sizes, int n_in,
                              void* d_out, int out_size)
{
    const float* hs  = (const float*)d_in[0];
    const float* Wqk = (const float*)d_in[1];
    const float* bqk = (const float*)d_in[2];
    const float* Wv  = (const float*)d_in[3];
    const float* bv  = (const float*)d_in[4];
    const float* Wo  = (const float*)d_in[5];
    const float* bo  = (const float*)d_in[6];
    float* out = (float*)d_out;

    float *qk, *v, *y;
    cudaGetSymbolAddress((void**)&qk, g_qk);
    cudaGetSymbolAddress((void**)&v,  g_v);
    cudaGetSymbolAddress((void**)&y,  g_y);

    cudaFuncSetAttribute(attn_kernel,
                         cudaFuncAttributeMaxDynamicSharedMemorySize, ATTN_SMEM);
    cudaFuncSetAttribute(gemm_bf16x3_kernel,
                         cudaFuncAttributeMaxDynamicSharedMemorySize, GEMM_SMEM);

    dim3 ggrid(CCH/128, MTOK/128);   // (8, 32)
    gemm_bf16x3_kernel<<<ggrid, 256, GEMM_SMEM>>>(hs, Wqk, bqk, qk);
    gemm_bf16x3_kernel<<<ggrid, 256, GEMM_SMEM>>>(hs, Wv,  bv,  v);

    attn_kernel<<<dim3(TT/64, BB*HH), 256, ATTN_SMEM>>>(qk, v, y);

    gemm_bf16x3_kernel<<<ggrid, 256, GEMM_SMEM>>>(y, Wo, bo, out);
}

// round 5
// speedup vs baseline: 2.2845x; 1.5970x over previous
#include <cuda_runtime.h>
#include <cuda_bf16.h>
#include <cstdint>

#define BB 2
#define TT 2048
#define CCH 1024
#define HH 16
#define DD 64
#define MTOK (BB*TT)          // 4096 tokens

// Scratch (allocation-free rule: __device__ globals)
__device__ float g_qk[MTOK*CCH];
__device__ float g_v [MTOK*CCH];
__device__ float g_y [MTOK*CCH];

// ===========================================================================
// Shared mma/ldmatrix helpers
// ===========================================================================
__device__ __forceinline__ void mma_bf16(float c[4],
    const unsigned int a[4], const unsigned int b[2])
{
    asm volatile(
        "mma.sync.aligned.m16n8k16.row.col.f32.bf16.bf16.f32 "
        "{%0,%1,%2,%3}, {%4,%5,%6,%7}, {%8,%9}, {%0,%1,%2,%3};"
        : "+f"(c[0]), "+f"(c[1]), "+f"(c[2]), "+f"(c[3])
        : "r"(a[0]), "r"(a[1]), "r"(a[2]), "r"(a[3]), "r"(b[0]), "r"(b[1]));
}

__device__ __forceinline__ void ldsm4(const __nv_bfloat16* base, int row0,
    int kc, int lane, int stride, unsigned int r[4])
{
    const __nv_bfloat16* p = base + (row0 + (lane & 15)) * stride
                                  + kc + ((lane >> 4) << 3);
    unsigned int addr = (unsigned int)__cvta_generic_to_shared(p);
    asm volatile("ldmatrix.sync.aligned.m8n8.x4.shared.b16 {%0,%1,%2,%3}, [%4];"
        : "=r"(r[0]), "=r"(r[1]), "=r"(r[2]), "=r"(r[3]) : "r"(addr));
}

__device__ __forceinline__ void ldsm2(const __nv_bfloat16* base, int row0,
    int kc, int lane, int stride, unsigned int r[2])
{
    const __nv_bfloat16* p = base + (row0 + (lane & 7)) * stride
                                  + kc + (((lane >> 3) & 1) << 3);
    unsigned int addr = (unsigned int)__cvta_generic_to_shared(p);
    asm volatile("ldmatrix.sync.aligned.m8n8.x2.shared.b16 {%0,%1}, [%2];"
        : "=r"(r[0]), "=r"(r[1]) : "r"(addr));
}

__device__ __forceinline__ void split_bf16(float x,
    __nv_bfloat16& h, __nv_bfloat16& l)
{
    h = __float2bfloat16_rn(x);
    l = __float2bfloat16_rn(x - __bfloat162float(h));
}

// ===========================================================================
// bf16x3 split-precision tensor-core GEMM (unchanged from R4 — passing)
//   Cout[M,N] = A[M,K] @ W[N,K]^T + bias[N],  M=4096, N=K=1024
// ===========================================================================
#define GK   1024
#define SSTR 40
#define GT   (128*SSTR)
#define GSTAGE (4*GT)
#define GEMM_SMEM (2*GSTAGE*2)

__global__ __launch_bounds__(256) void gemm_bf16x3_kernel(
    const float* __restrict__ A, const float* __restrict__ W,
    const float* __restrict__ bias, float* __restrict__ Cout)
{
    extern __shared__ __nv_bfloat16 smem[];

    const int tid  = threadIdx.x;
    const int wid  = tid >> 5;
    const int lane = tid & 31;
    const int g    = lane >> 2;
    const int t4   = lane & 3;
    const int m0   = blockIdx.y * 128;
    const int n0   = blockIdx.x * 128;
    const int wm   = (wid & 1) * 64;
    const int wn   = (wid >> 1) * 32;

    const int lr = tid >> 3;
    const int lc = (tid & 7) * 4;

    float acc[4][4][4];
#pragma unroll
    for (int i = 0; i < 4; i++)
#pragma unroll
        for (int j = 0; j < 4; j++)
#pragma unroll
            for (int r = 0; r < 4; r++) acc[i][j][r] = 0.f;

    auto g_load = [&](const float* P, int row0, int kk, float4 v[4]) {
#pragma unroll
        for (int p = 0; p < 4; p++)
            v[p] = *(const float4*)&P[(size_t)(row0 + p*32 + lr) * GK + kk + lc];
    };

    auto cvt_store = [&](__nv_bfloat16* dh, __nv_bfloat16* dl, const float4 v[4]) {
#pragma unroll
        for (int p = 0; p < 4; p++) {
            const int r = p*32 + lr;
            float f[4] = {v[p].x, v[p].y, v[p].z, v[p].w};
            __nv_bfloat16 h[4], l[4];
#pragma unroll
            for (int q = 0; q < 4; q++) split_bf16(f[q], h[q], l[q]);
            *(__nv_bfloat162*)&dh[r*SSTR + lc    ] = __nv_bfloat162(h[0], h[1]);
            *(__nv_bfloat162*)&dh[r*SSTR + lc + 2] = __nv_bfloat162(h[2], h[3]);
            *(__nv_bfloat162*)&dl[r*SSTR + lc    ] = __nv_bfloat162(l[0], l[1]);
            *(__nv_bfloat162*)&dl[r*SSTR + lc + 2] = __nv_bfloat162(l[2], l[3]);
        }
    };

    {
        float4 ta[4], tb[4];
        g_load(A, m0, 0, ta);
        g_load(W, n0, 0, tb);
        cvt_store(smem,        smem +   GT, ta);
        cvt_store(smem + 2*GT, smem + 3*GT, tb);
    }
    __syncthreads();

    const int nk = GK / 32;
    float4 ra[4], rb[4];
    for (int kt = 0; kt < nk; kt++) {
        const int s = kt & 1;
        __nv_bfloat16* sAh = smem + s*GSTAGE;
        __nv_bfloat16* sAl = sAh + GT;
        __nv_bfloat16* sBh = sAh + 2*GT;
        __nv_bfloat16* sBl = sAh + 3*GT;

        const bool more = (kt + 1 < nk);
        if (more) {
            g_load(A, m0, (kt+1)*32, ra);
            g_load(W, n0, (kt+1)*32, rb);
        }

#pragma unroll
        for (int ks = 0; ks < 32; ks += 16) {
            unsigned int ah[4][4], al[4][4], bh[4][2], bl[4][2];
#pragma unroll
            for (int i = 0; i < 4; i++) {
                ldsm4(sAh, wm + i*16, ks, lane, SSTR, ah[i]);
                ldsm4(sAl, wm + i*16, ks, lane, SSTR, al[i]);
            }
#pragma unroll
            for (int j = 0; j < 4; j++) {
                ldsm2(sBh, wn + j*8, ks, lane, SSTR, bh[j]);
                ldsm2(sBl, wn + j*8, ks, lane, SSTR, bl[j]);
            }
#pragma unroll
            for (int i = 0; i < 4; i++)
#pragma unroll
                for (int j = 0; j < 4; j++) {
                    mma_bf16(acc[i][j], ah[i], bh[j]);
                    mma_bf16(acc[i][j], ah[i], bl[j]);
                    mma_bf16(acc[i][j], al[i], bh[j]);
                }
        }

        if (more) {
            const int s2 = s ^ 1;
            __nv_bfloat16* dAh = smem + s2*GSTAGE;
            cvt_store(dAh,        dAh +   GT, ra);
            cvt_store(dAh + 2*GT, dAh + 3*GT, rb);
        }
        __syncthreads();
    }

#pragma unroll
    for (int i = 0; i < 4; i++)
#pragma unroll
        for (int j = 0; j < 4; j++) {
            const int r = m0 + wm + i*16 + g;
            const int c = n0 + wn + j*8 + t4*2;
            const float b0v = bias[c], b1v = bias[c+1];
            float2 v0 = {acc[i][j][0] + b0v, acc[i][j][1] + b1v};
            float2 v1 = {acc[i][j][2] + b0v, acc[i][j][3] + b1v};
            *(float2*)&Cout[(size_t)r       * CCH + c] = v0;
            *(float2*)&Cout[(size_t)(r + 8) * CCH + c] = v1;
        }
}

// ===========================================================================
// Tensor-core flash attention, bf16x3 split on both QK^T and PV.
// CTA: 64 queries x one (b,h). 4 warps; warp w owns rows [16w,16w+16).
// Smem: Qh/Ql, Kh/Kl row-major [row][d]; Vh/Vl transposed [d][row]. stride 72.
// ===========================================================================
#define ASTR 72
#define ATILE (64*ASTR)
#define ATTN_SMEM (6*ATILE*2)     // 55296 bytes

__global__ __launch_bounds__(128) void attn_mma_kernel(
    const float* __restrict__ qk, const float* __restrict__ v,
    float* __restrict__ y)
{
    extern __shared__ __nv_bfloat16 smA[];
    __nv_bfloat16* Qh = smA;
    __nv_bfloat16* Ql = smA +   ATILE;
    __nv_bfloat16* Kh = smA + 2*ATILE;
    __nv_bfloat16* Kl = smA + 3*ATILE;
    __nv_bfloat16* Vh = smA + 4*ATILE;   // [d][row]
    __nv_bfloat16* Vl = smA + 5*ATILE;

    const int tid  = threadIdx.x;
    const int wid  = tid >> 5;
    const int lane = tid & 31;
    const int g    = lane >> 2;
    const int t4   = lane & 3;
    const int qi = blockIdx.x;
    const int bh = blockIdx.y;
    const int b  = bh / HH, h = bh % HH;
    const int q0 = qi * 64;
    const size_t base = ((size_t)b * TT) * CCH + (size_t)h * DD;

    // ---- load Q tile, split hi/lo, row-major ----
#pragma unroll
    for (int p = 0; p < 8; p++) {
        int f  = tid + 128*p;            // 0..1023
        int r  = f >> 4;                 // 0..63
        int c4 = (f & 15) * 4;           // 0..60
        float4 vq = *(const float4*)&qk[base + (size_t)(q0 + r)*CCH + c4];
        float fv[4] = {vq.x, vq.y, vq.z, vq.w};
        __nv_bfloat16 hh[4], ll[4];
#pragma unroll
        for (int q = 0; q < 4; q++) split_bf16(fv[q], hh[q], ll[q]);
        *(__nv_bfloat162*)&Qh[r*ASTR + c4    ] = __nv_bfloat162(hh[0], hh[1]);
        *(__nv_bfloat162*)&Qh[r*ASTR + c4 + 2] = __nv_bfloat162(hh[2], hh[3]);
        *(__nv_bfloat162*)&Ql[r*ASTR + c4    ] = __nv_bfloat162(ll[0], ll[1]);
        *(__nv_bfloat162*)&Ql[r*ASTR + c4 + 2] = __nv_bfloat162(ll[2], ll[3]);
    }

    float m0r = -1e30f, m1r = -1e30f, l0r = 0.f, l1r = 0.f;
    float o[8][4];
#pragma unroll
    for (int j = 0; j < 8; j++)
#pragma unroll
        for (int r = 0; r < 4; r++) o[j][r] = 0.f;

    for (int kv = 0; kv <= qi; kv++) {
        __syncthreads();   // prior-iter smem readers done (first iter: Q fill fence below)
        // ---- load K (row-major) and V (transposed) tiles, split hi/lo ----
#pragma unroll
        for (int p = 0; p < 8; p++) {
            int f  = tid + 128*p;
            int r  = f >> 4;
            int c4 = (f & 15) * 4;
            size_t gg = base + (size_t)(kv*64 + r)*CCH + c4;
            float4 kvl = *(const float4*)&qk[gg];
            float fk[4] = {kvl.x, kvl.y, kvl.z, kvl.w};
            __nv_bfloat16 hh[4], ll[4];
#pragma unroll
            for (int q = 0; q < 4; q++) split_bf16(fk[q], hh[q], ll[q]);
            *(__nv_bfloat162*)&Kh[r*ASTR + c4    ] = __nv_bfloat162(hh[0], hh[1]);
            *(__nv_bfloat162*)&Kh[r*ASTR + c4 + 2] = __nv_bfloat162(hh[2], hh[3]);
            *(__nv_bfloat162*)&Kl[r*ASTR + c4    ] = __nv_bfloat162(ll[0], ll[1]);
            *(__nv_bfloat162*)&Kl[r*ASTR + c4 + 2] = __nv_bfloat162(ll[2], ll[3]);

            float4 vvl = *(const float4*)&v[gg];
            float fvilla[4] = {vvl.x, vvl.y, vvl.z, vvl.w};
#pragma unroll
            for (int q = 0; q < 4; q++) {
                __nv_bfloat16 vh, vl2;
                split_bf16(fvilla[q], vh, vl2);
                Vh[(c4 + q)*ASTR + r] = vh;
                Vl[(c4 + q)*ASTR + r] = vl2;
            }
        }
        __syncthreads();

        // ---- S = Q @ K^T (split x3) ----
        float s[8][4];
#pragma unroll
        for (int j = 0; j < 8; j++)
#pragma unroll
            for (int r = 0; r < 4; r++) s[j][r] = 0.f;

#pragma unroll
        for (int ks = 0; ks < 4; ks++) {
            unsigned int ah[4], al[4];
            ldsm4(Qh, wid*16, ks*16, lane, ASTR, ah);
            ldsm4(Ql, wid*16, ks*16, lane, ASTR, al);
#pragma unroll
            for (int j = 0; j < 8; j++) {
                unsigned int kbh[2], kbl[2];
                ldsm2(Kh, j*8, ks*16, lane, ASTR, kbh);
                ldsm2(Kl, j*8, ks*16, lane, ASTR, kbl);
                mma_bf16(s[j], ah, kbh);
                mma_bf16(s[j], ah, kbl);
                mma_bf16(s[j], al, kbh);
            }
        }

        // ---- scale + causal mask ----
        const float scale = 0.125f;
        const int row0 = wid*16 + g;      // local row of c0/c1
        const int row1 = row0 + 8;        // local row of c2/c3
        if (kv == qi) {
#pragma unroll
            for (int j = 0; j < 8; j++) {
                const int c0 = j*8 + 2*t4, c1 = c0 + 1;
                s[j][0] = (c0 > row0) ? -1e30f : s[j][0]*scale;
                s[j][1] = (c1 > row0) ? -1e30f : s[j][1]*scale;
                s[j][2] = (c0 > row1) ? -1e30f : s[j][2]*scale;
                s[j][3] = (c1 > row1) ? -1e30f : s[j][3]*scale;
            }
        } else {
#pragma unroll
            for (int j = 0; j < 8; j++)
#pragma unroll
                for (int r = 0; r < 4; r++) s[j][r] *= scale;
        }

        // ---- online softmax (quad reductions over t4 lanes) ----
        float mx0 = -1e30f, mx1 = -1e30f;
#pragma unroll
        for (int j = 0; j < 8; j++) {
            mx0 = fmaxf(mx0, fmaxf(s[j][0], s[j][1]));
            mx1 = fmaxf(mx1, fmaxf(s[j][2], s[j][3]));
        }
        mx0 = fmaxf(mx0, __shfl_xor_sync(0xffffffffu, mx0, 1));
        mx0 = fmaxf(mx0, __shfl_xor_sync(0xffffffffu, mx0, 2));
        mx1 = fmaxf(mx1, __shfl_xor_sync(0xffffffffu, mx1, 1));
        mx1 = fmaxf(mx1, __shfl_xor_sync(0xffffffffu, mx1, 2));

        const float mn0 = fmaxf(m0r, mx0), mn1 = fmaxf(m1r, mx1);
        const float cr0 = __expf(m0r - mn0), cr1 = __expf(m1r - mn1);
        m0r = mn0; m1r = mn1;

        float sum0 = 0.f, sum1 = 0.f;
#pragma unroll
        for (int j = 0; j < 8; j++) {
            s[j][0] = __expf(s[j][0] - mn0);
            s[j][1] = __expf(s[j][1] - mn0);
            s[j][2] = __expf(s[j][2] - mn1);
            s[j][3] = __expf(s[j][3] - mn1);
            sum0 += s[j][0] + s[j][1];
            sum1 += s[j][2] + s[j][3];
        }
        sum0 += __shfl_xor_sync(0xffffffffu, sum0, 1);
        sum0 += __shfl_xor_sync(0xffffffffu, sum0, 2);
        sum1 += __shfl_xor_sync(0xffffffffu, sum1, 1);
        sum1 += __shfl_xor_sync(0xffffffffu, sum1, 2);
        l0r = l0r*cr0 + sum0;
        l1r = l1r*cr1 + sum1;

#pragma unroll
        for (int j = 0; j < 8; j++) {
            o[j][0] *= cr0; o[j][1] *= cr0;
            o[j][2] *= cr1; o[j][3] *= cr1;
        }

        // ---- O += P @ V (split x3), P fragments built in registers ----
#pragma unroll
        for (int c = 0; c < 4; c++) {
            unsigned int aPh[4], aPl[4];
#pragma unroll
            for (int half = 0; half < 2; half++) {   // tiles 2c, 2c+1
                const int jt = 2*c + half;
                __nv_bfloat16 h0, l0, h1, l1, h2, l2, h3, l3;
                split_bf16(s[jt][0], h0, l0);
                split_bf16(s[jt][1], h1, l1);
                split_bf16(s[jt][2], h2, l2);
                split_bf16(s[jt][3], h3, l3);
                __nv_bfloat162 H01(h0, h1), H23(h2, h3), L01(l0, l1), L23(l2, l3);
                aPh[2*half    ] = *(unsigned int*)&H01;
                aPh[2*half + 1] = *(unsigned int*)&H23;
                aPl[2*half    ] = *(unsigned int*)&L01;
                aPl[2*half + 1] = *(unsigned int*)&L23;
            }
#pragma unroll
            for (int j = 0; j < 8; j++) {
                unsigned int vbh[2], vbl[2];
                ldsm2(Vh, j*8, c*16, lane, ASTR, vbh);
                ldsm2(Vl, j*8, c*16, lane, ASTR, vbl);
                mma_bf16(o[j], aPh, vbh);
                mma_bf16(o[j], aPh, vbl);
                mma_bf16(o[j], aPl, vbh);
            }
        }
    }

    // ---- normalize + write y ----
    const float inv0 = 1.f / l0r, inv1 = 1.f / l1r;
    const int r0 = q0 + wid*16 + g;
    const int r1 = r0 + 8;
#pragma unroll
    for (int j = 0; j < 8; j++) {
        const int c = j*8 + 2*t4;
        float2 w0 = {o[j][0]*inv0, o[j][1]*inv0};
        float2 w1 = {o[j][2]*inv1, o[j][3]*inv1};
        *(float2*)&y[base + (size_t)r0*CCH + c] = w0;
        *(float2*)&y[base + (size_t)r1*CCH + c] = w1;
    }
}

// ---------------------------------------------------------------------------
extern "C" void kernel_launch(void* const* d_in, const int* in_sizes, int n_in,
                              void* d_out, int out_size)
{
    const float* hs  = (const float*)d_in[0];
    const float* Wqk = (const float*)d_in[1];
    const float* bqk = (const float*)d_in[2];
    const float* Wv  = (const float*)d_in[3];
    const float* bv  = (const float*)d_in[4];
    const float* Wo  = (const float*)d_in[5];
    const float* bo  = (const float*)d_in[6];
    float* out = (float*)d_out;

    float *qk, *v, *y;
    cudaGetSymbolAddress((void**)&qk, g_qk);
    cudaGetSymbolAddress((void**)&v,  g_v);
    cudaGetSymbolAddress((void**)&y,  g_y);

    cudaFuncSetAttribute(attn_mma_kernel,
                         cudaFuncAttributeMaxDynamicSharedMemorySize, ATTN_SMEM);
    cudaFuncSetAttribute(gemm_bf16x3_kernel,
                         cudaFuncAttributeMaxDynamicSharedMemorySize, GEMM_SMEM);

    dim3 ggrid(CCH/128, MTOK/128);   // (8, 32)
    gemm_bf16x3_kernel<<<ggrid, 256, GEMM_SMEM>>>(hs, Wqk, bqk, qk);
    gemm_bf16x3_kernel<<<ggrid, 256, GEMM_SMEM>>>(hs, Wv,  bv,  v);

    attn_mma_kernel<<<dim3(TT/64, BB*HH), 128, ATTN_SMEM>>>(qk, v, y);

    gemm_bf16x3_kernel<<<ggrid, 256, GEMM_SMEM>>>(y, Wo, bo, out);
}

// round 6
// speedup vs baseline: 2.8561x; 1.2502x over previous
#include <cuda_runtime.h>
#include <cuda_bf16.h>
#include <cstdint>

#define BB 2
#define TT 2048
#define CCH 1024
#define HH 16
#define DD 64
#define MTOK (BB*TT)          // 4096 tokens
#define GK   1024

// ---------------------------------------------------------------------------
// Scratch (allocation-free rule: __device__ globals), all bf16 hi/lo pairs
// ---------------------------------------------------------------------------
__device__ __nv_bfloat16 g_hs_h[MTOK*CCH],  g_hs_l[MTOK*CCH];
__device__ __nv_bfloat16 g_Wqk_h[CCH*CCH],  g_Wqk_l[CCH*CCH];
__device__ __nv_bfloat16 g_Wv_h [CCH*CCH],  g_Wv_l [CCH*CCH];
__device__ __nv_bfloat16 g_Wo_h [CCH*CCH],  g_Wo_l [CCH*CCH];
__device__ __nv_bfloat16 g_qk_h[MTOK*CCH],  g_qk_l[MTOK*CCH];
__device__ __nv_bfloat16 g_v_h [MTOK*CCH],  g_v_l [MTOK*CCH];
__device__ __nv_bfloat16 g_y_h [MTOK*CCH],  g_y_l [MTOK*CCH];

// ===========================================================================
// Helpers
// ===========================================================================
__device__ __forceinline__ void split_bf16(float x,
    __nv_bfloat16& h, __nv_bfloat16& l)
{
    h = __float2bfloat16_rn(x);
    l = __float2bfloat16_rn(x - __bfloat162float(h));
}

__device__ __forceinline__ void mma_bf16(float c[4],
    const unsigned int a[4], const unsigned int b[2])
{
    asm volatile(
        "mma.sync.aligned.m16n8k16.row.col.f32.bf16.bf16.f32 "
        "{%0,%1,%2,%3}, {%4,%5,%6,%7}, {%8,%9}, {%0,%1,%2,%3};"
        : "+f"(c[0]), "+f"(c[1]), "+f"(c[2]), "+f"(c[3])
        : "r"(a[0]), "r"(a[1]), "r"(a[2]), "r"(a[3]), "r"(b[0]), "r"(b[1]));
}

__device__ __forceinline__ void ldsm4(const __nv_bfloat16* base, int row0,
    int kc, int lane, int stride, unsigned int r[4])
{
    const __nv_bfloat16* p = base + (row0 + (lane & 15)) * stride
                                  + kc + ((lane >> 4) << 3);
    unsigned int addr = (unsigned int)__cvta_generic_to_shared(p);
    asm volatile("ldmatrix.sync.aligned.m8n8.x4.shared.b16 {%0,%1,%2,%3}, [%4];"
        : "=r"(r[0]), "=r"(r[1]), "=r"(r[2]), "=r"(r[3]) : "r"(addr));
}

__device__ __forceinline__ void ldsm2(const __nv_bfloat16* base, int row0,
    int kc, int lane, int stride, unsigned int r[2])
{
    const __nv_bfloat16* p = base + (row0 + (lane & 7)) * stride
                                  + kc + (((lane >> 3) & 1) << 3);
    unsigned int addr = (unsigned int)__cvta_generic_to_shared(p);
    asm volatile("ldmatrix.sync.aligned.m8n8.x2.shared.b16 {%0,%1}, [%2];"
        : "=r"(r[0]), "=r"(r[1]) : "r"(addr));
}

// transposed B-fragment load: smem tile is [k][n] row-major (rows = k)
__device__ __forceinline__ void ldsm2t(const __nv_bfloat16* base, int k0,
    int n0, int lane, int stride, unsigned int r[2])
{
    const __nv_bfloat16* p = base
        + (k0 + (lane & 7) + ((lane >> 3) & 1) * 8) * stride + n0;
    unsigned int addr = (unsigned int)__cvta_generic_to_shared(p);
    asm volatile("ldmatrix.sync.aligned.m8n8.x2.trans.shared.b16 {%0,%1}, [%2];"
        : "=r"(r[0]), "=r"(r[1]) : "r"(addr));
}

// ===========================================================================
// Elementwise fp32 -> bf16 hi/lo split (pre-pass)
// ===========================================================================
__global__ void split_kernel(const float4* __restrict__ in,
    __nv_bfloat162* __restrict__ h2, __nv_bfloat162* __restrict__ l2, int n4)
{
    int i = blockIdx.x * blockDim.x + threadIdx.x;
    if (i >= n4) return;
    float4 v = in[i];
    float f[4] = {v.x, v.y, v.z, v.w};
    __nv_bfloat16 h[4], l[4];
#pragma unroll
    for (int q = 0; q < 4; q++) split_bf16(f[q], h[q], l[q]);
    h2[2*i    ] = __nv_bfloat162(h[0], h[1]);
    h2[2*i + 1] = __nv_bfloat162(h[2], h[3]);
    l2[2*i    ] = __nv_bfloat162(l[0], l[1]);
    l2[2*i + 1] = __nv_bfloat162(l[2], l[3]);
}

// ===========================================================================
// bf16x3 tensor-core GEMM, pre-split operands, cp.async double buffer.
//   C[M,N] = (Ah+Al)[M,K] @ (Wh+Wl)[N,K]^T + bias (3-term split product)
// 128x128 CTA tile, BK=32, 256 threads (8 warps, 64x32 each), 2 CTAs/SM.
// Output: fp32 Cout OR bf16 hi/lo pair (outh/outl).
// ===========================================================================
#define SSTR 40
#define KTILE (128*SSTR)
#define STAGE_ELEMS (4*KTILE)
#define GEMM_SMEM (2*STAGE_ELEMS*2)     // 2 stages, bytes

__global__ __launch_bounds__(256, 2) void gemm_pre_kernel(
    const __nv_bfloat16* __restrict__ Ah_g, const __nv_bfloat16* __restrict__ Al_g,
    const __nv_bfloat16* __restrict__ Wh_g, const __nv_bfloat16* __restrict__ Wl_g,
    const float* __restrict__ bias, float* __restrict__ Cout,
    __nv_bfloat16* __restrict__ outh, __nv_bfloat16* __restrict__ outl)
{
    extern __shared__ __nv_bfloat16 smem[];

    const int tid  = threadIdx.x;
    const int wid  = tid >> 5;
    const int lane = tid & 31;
    const int g    = lane >> 2;
    const int t4   = lane & 3;
    const int m0   = blockIdx.y * 128;
    const int n0   = blockIdx.x * 128;
    const int wm   = (wid & 1) * 64;
    const int wn   = (wid >> 1) * 32;

    const __nv_bfloat16* srcs[4] = {Ah_g, Al_g, Wh_g, Wl_g};

    float acc[4][4][4];
#pragma unroll
    for (int i = 0; i < 4; i++)
#pragma unroll
        for (int j = 0; j < 4; j++)
#pragma unroll
            for (int r = 0; r < 4; r++) acc[i][j][r] = 0.f;

    auto issue_stage = [&](int kt, int s) {
        const int kk = kt * 32;
#pragma unroll
        for (int p = 0; p < 8; p++) {
            int idx  = tid + 256*p;          // 0..2047
            int tile = idx >> 9;             // 0..3
            int rem  = idx & 511;
            int r    = rem >> 2;             // 0..127
            int c    = rem & 3;              // 0..3 (16B chunks)
            int grow = ((tile < 2) ? m0 : n0) + r;
            const __nv_bfloat16* src = srcs[tile] + (size_t)grow * GK + kk + c*8;
            __nv_bfloat16* dst = smem + s*STAGE_ELEMS + tile*KTILE + r*SSTR + c*8;
            unsigned int daddr = (unsigned int)__cvta_generic_to_shared(dst);
            asm volatile("cp.async.cg.shared.global [%0], [%1], 16;\n"
                         :: "r"(daddr), "l"(src));
        }
        asm volatile("cp.async.commit_group;\n");
    };

    issue_stage(0, 0);

    const int nk = GK / 32;
    for (int kt = 0; kt < nk; kt++) {
        const int s = kt & 1;
        const bool more = (kt + 1 < nk);
        if (more) {
            issue_stage(kt + 1, s ^ 1);
            asm volatile("cp.async.wait_group 1;\n");
        } else {
            asm volatile("cp.async.wait_group 0;\n");
        }
        __syncthreads();

        const __nv_bfloat16* sAh = smem + s*STAGE_ELEMS;
        const __nv_bfloat16* sAl = sAh + KTILE;
        const __nv_bfloat16* sWh = sAh + 2*KTILE;
        const __nv_bfloat16* sWl = sAh + 3*KTILE;

#pragma unroll
        for (int ks = 0; ks < 32; ks += 16) {
            unsigned int ah[4][4], al[4][4], bh[4][2], bl[4][2];
#pragma unroll
            for (int i = 0; i < 4; i++) {
                ldsm4(sAh, wm + i*16, ks, lane, SSTR, ah[i]);
                ldsm4(sAl, wm + i*16, ks, lane, SSTR, al[i]);
            }
#pragma unroll
            for (int j = 0; j < 4; j++) {
                ldsm2(sWh, wn + j*8, ks, lane, SSTR, bh[j]);
                ldsm2(sWl, wn + j*8, ks, lane, SSTR, bl[j]);
            }
#pragma unroll
            for (int i = 0; i < 4; i++)
#pragma unroll
                for (int j = 0; j < 4; j++) {
                    mma_bf16(acc[i][j], ah[i], bh[j]);
                    mma_bf16(acc[i][j], ah[i], bl[j]);
                    mma_bf16(acc[i][j], al[i], bh[j]);
                }
        }
        __syncthreads();
    }

    // epilogue
#pragma unroll
    for (int i = 0; i < 4; i++)
#pragma unroll
        for (int j = 0; j < 4; j++) {
            const int r = m0 + wm + i*16 + g;
            const int c = n0 + wn + j*8 + t4*2;
            const float b0v = bias[c], b1v = bias[c+1];
            float v00 = acc[i][j][0] + b0v, v01 = acc[i][j][1] + b1v;
            float v10 = acc[i][j][2] + b0v, v11 = acc[i][j][3] + b1v;
            if (outl) {
                __nv_bfloat16 h0,l0,h1,l1,h2,l2,h3,l3;
                split_bf16(v00, h0, l0); split_bf16(v01, h1, l1);
                split_bf16(v10, h2, l2); split_bf16(v11, h3, l3);
                *(__nv_bfloat162*)&outh[(size_t)r      *CCH + c] = __nv_bfloat162(h0, h1);
                *(__nv_bfloat162*)&outh[(size_t)(r + 8)*CCH + c] = __nv_bfloat162(h2, h3);
                *(__nv_bfloat162*)&outl[(size_t)r      *CCH + c] = __nv_bfloat162(l0, l1);
                *(__nv_bfloat162*)&outl[(size_t)(r + 8)*CCH + c] = __nv_bfloat162(l2, l3);
            } else {
                float2 w0 = {v00, v01}, w1 = {v10, v11};
                *(float2*)&Cout[(size_t)r       * CCH + c] = w0;
                *(float2*)&Cout[(size_t)(r + 8) * CCH + c] = w1;
            }
        }
}

// ===========================================================================
// Tensor-core flash attention on pre-split bf16 hi/lo operands.
// CTA: 64 queries x one (b,h). 4 warps. V kept [t][d]; B-frag via ldmatrix.trans.
// ===========================================================================
#define ASTR 72
#define ATILE (64*ASTR)
#define ATTN_SMEM (6*ATILE*2)     // 55296 bytes

__global__ __launch_bounds__(128) void attn_mma_kernel(
    const __nv_bfloat16* __restrict__ qkh, const __nv_bfloat16* __restrict__ qkl,
    const __nv_bfloat16* __restrict__ vgh, const __nv_bfloat16* __restrict__ vgl,
    __nv_bfloat16* __restrict__ yh, __nv_bfloat16* __restrict__ yl)
{
    extern __shared__ __nv_bfloat16 smA[];
    __nv_bfloat16* Qh = smA;
    __nv_bfloat16* Ql = smA +   ATILE;
    __nv_bfloat16* Kh = smA + 2*ATILE;
    __nv_bfloat16* Kl = smA + 3*ATILE;
    __nv_bfloat16* Vh = smA + 4*ATILE;   // [t][d]
    __nv_bfloat16* Vl = smA + 5*ATILE;

    const int tid  = threadIdx.x;
    const int wid  = tid >> 5;
    const int lane = tid & 31;
    const int g    = lane >> 2;
    const int t4   = lane & 3;
    const int qi = blockIdx.x;
    const int bh = blockIdx.y;
    const int b  = bh / HH, h = bh % HH;
    const int q0 = qi * 64;
    const size_t base = ((size_t)b * TT) * CCH + (size_t)h * DD;

    // ---- load Q tile (bare 16B copies) ----
#pragma unroll
    for (int p = 0; p < 4; p++) {
        int idx = tid + 128*p;           // 0..511
        int r   = idx >> 3;              // 0..63
        int c8  = (idx & 7) * 8;         // 0..56
        size_t gg = base + (size_t)(q0 + r)*CCH + c8;
        *(uint4*)&Qh[r*ASTR + c8] = *(const uint4*)&qkh[gg];
        *(uint4*)&Ql[r*ASTR + c8] = *(const uint4*)&qkl[gg];
    }

    float m0r = -1e30f, m1r = -1e30f, l0r = 0.f, l1r = 0.f;
    float o[8][4];
#pragma unroll
    for (int j = 0; j < 8; j++)
#pragma unroll
        for (int r = 0; r < 4; r++) o[j][r] = 0.f;

    for (int kv = 0; kv <= qi; kv++) {
        __syncthreads();   // prior-iter readers done (first iter covers Q fill)
#pragma unroll
        for (int p = 0; p < 4; p++) {
            int idx = tid + 128*p;
            int r   = idx >> 3;
            int c8  = (idx & 7) * 8;
            size_t gg = base + (size_t)(kv*64 + r)*CCH + c8;
            *(uint4*)&Kh[r*ASTR + c8] = *(const uint4*)&qkh[gg];
            *(uint4*)&Kl[r*ASTR + c8] = *(const uint4*)&qkl[gg];
            *(uint4*)&Vh[r*ASTR + c8] = *(const uint4*)&vgh[gg];
            *(uint4*)&Vl[r*ASTR + c8] = *(const uint4*)&vgl[gg];
        }
        __syncthreads();

        // ---- S = Q @ K^T (split x3) ----
        float s[8][4];
#pragma unroll
        for (int j = 0; j < 8; j++)
#pragma unroll
            for (int r = 0; r < 4; r++) s[j][r] = 0.f;

#pragma unroll
        for (int ks = 0; ks < 4; ks++) {
            unsigned int ah[4], al[4];
            ldsm4(Qh, wid*16, ks*16, lane, ASTR, ah);
            ldsm4(Ql, wid*16, ks*16, lane, ASTR, al);
#pragma unroll
            for (int j = 0; j < 8; j++) {
                unsigned int kbh[2], kbl[2];
                ldsm2(Kh, j*8, ks*16, lane, ASTR, kbh);
                ldsm2(Kl, j*8, ks*16, lane, ASTR, kbl);
                mma_bf16(s[j], ah, kbh);
                mma_bf16(s[j], ah, kbl);
                mma_bf16(s[j], al, kbh);
            }
        }

        // ---- scale + causal mask ----
        const float scale = 0.125f;
        const int row0 = wid*16 + g;
        const int row1 = row0 + 8;
        if (kv == qi) {
#pragma unroll
            for (int j = 0; j < 8; j++) {
                const int c0 = j*8 + 2*t4, c1 = c0 + 1;
                s[j][0] = (c0 > row0) ? -1e30f : s[j][0]*scale;
                s[j][1] = (c1 > row0) ? -1e30f : s[j][1]*scale;
                s[j][2] = (c0 > row1) ? -1e30f : s[j][2]*scale;
                s[j][3] = (c1 > row1) ? -1e30f : s[j][3]*scale;
            }
        } else {
#pragma unroll
            for (int j = 0; j < 8; j++)
#pragma unroll
                for (int r = 0; r < 4; r++) s[j][r] *= scale;
        }

        // ---- online softmax (quad reductions) ----
        float mx0 = -1e30f, mx1 = -1e30f;
#pragma unroll
        for (int j = 0; j < 8; j++) {
            mx0 = fmaxf(mx0, fmaxf(s[j][0], s[j][1]));
            mx1 = fmaxf(mx1, fmaxf(s[j][2], s[j][3]));
        }
        mx0 = fmaxf(mx0, __shfl_xor_sync(0xffffffffu, mx0, 1));
        mx0 = fmaxf(mx0, __shfl_xor_sync(0xffffffffu, mx0, 2));
        mx1 = fmaxf(mx1, __shfl_xor_sync(0xffffffffu, mx1, 1));
        mx1 = fmaxf(mx1, __shfl_xor_sync(0xffffffffu, mx1, 2));

        const float mn0 = fmaxf(m0r, mx0), mn1 = fmaxf(m1r, mx1);
        const float cr0 = __expf(m0r - mn0), cr1 = __expf(m1r - mn1);
        m0r = mn0; m1r = mn1;

        float sum0 = 0.f, sum1 = 0.f;
#pragma unroll
        for (int j = 0; j < 8; j++) {
            s[j][0] = __expf(s[j][0] - mn0);
            s[j][1] = __expf(s[j][1] - mn0);
            s[j][2] = __expf(s[j][2] - mn1);
            s[j][3] = __expf(s[j][3] - mn1);
            sum0 += s[j][0] + s[j][1];
            sum1 += s[j][2] + s[j][3];
        }
        sum0 += __shfl_xor_sync(0xffffffffu, sum0, 1);
        sum0 += __shfl_xor_sync(0xffffffffu, sum0, 2);
        sum1 += __shfl_xor_sync(0xffffffffu, sum1, 1);
        sum1 += __shfl_xor_sync(0xffffffffu, sum1, 2);
        l0r = l0r*cr0 + sum0;
        l1r = l1r*cr1 + sum1;

#pragma unroll
        for (int j = 0; j < 8; j++) {
            o[j][0] *= cr0; o[j][1] *= cr0;
            o[j][2] *= cr1; o[j][3] *= cr1;
        }

        // ---- O += P @ V (split x3), P frags in registers, V via ldsm.trans ----
#pragma unroll
        for (int c = 0; c < 4; c++) {
            unsigned int aPh[4], aPl[4];
#pragma unroll
            for (int half = 0; half < 2; half++) {
                const int jt = 2*c + half;
                __nv_bfloat16 h0,l0,h1,l1,h2,l2,h3,l3;
                split_bf16(s[jt][0], h0, l0);
                split_bf16(s[jt][1], h1, l1);
                split_bf16(s[jt][2], h2, l2);
                split_bf16(s[jt][3], h3, l3);
                __nv_bfloat162 H01(h0, h1), H23(h2, h3), L01(l0, l1), L23(l2, l3);
                aPh[2*half    ] = *(unsigned int*)&H01;
                aPh[2*half + 1] = *(unsigned int*)&H23;
                aPl[2*half    ] = *(unsigned int*)&L01;
                aPl[2*half + 1] = *(unsigned int*)&L23;
            }
#pragma unroll
            for (int j = 0; j < 8; j++) {
                unsigned int vbh[2], vbl[2];
                ldsm2t(Vh, c*16, j*8, lane, ASTR, vbh);
                ldsm2t(Vl, c*16, j*8, lane, ASTR, vbl);
                mma_bf16(o[j], aPh, vbh);
                mma_bf16(o[j], aPh, vbl);
                mma_bf16(o[j], aPl, vbh);
            }
        }
    }

    // ---- normalize + write y as bf16 hi/lo ----
    const float inv0 = 1.f / l0r, inv1 = 1.f / l1r;
    const int r0 = q0 + wid*16 + g;
    const int r1 = r0 + 8;
#pragma unroll
    for (int j = 0; j < 8; j++) {
        const int c = j*8 + 2*t4;
        float v00 = o[j][0]*inv0, v01 = o[j][1]*inv0;
        float v10 = o[j][2]*inv1, v11 = o[j][3]*inv1;
        __nv_bfloat16 h0,l0,h1,l1,h2,l2,h3,l3;
        split_bf16(v00, h0, l0); split_bf16(v01, h1, l1);
        split_bf16(v10, h2, l2); split_bf16(v11, h3, l3);
        *(__nv_bfloat162*)&yh[base + (size_t)r0*CCH + c] = __nv_bfloat162(h0, h1);
        *(__nv_bfloat162*)&yh[base + (size_t)r1*CCH + c] = __nv_bfloat162(h2, h3);
        *(__nv_bfloat162*)&yl[base + (size_t)r0*CCH + c] = __nv_bfloat162(l0, l1);
        *(__nv_bfloat162*)&yl[base + (size_t)r1*CCH + c] = __nv_bfloat162(l2, l3);
    }
}

// ---------------------------------------------------------------------------
extern "C" void kernel_launch(void* const* d_in, const int* in_sizes, int n_in,
                              void* d_out, int out_size)
{
    const float* hs  = (const float*)d_in[0];
    const float* Wqk = (const float*)d_in[1];
    const float* bqk = (const float*)d_in[2];
    const float* Wv  = (const float*)d_in[3];
    const float* bv  = (const float*)d_in[4];
    const float* Wo  = (const float*)d_in[5];
    const float* bo  = (const float*)d_in[6];
    float* out = (float*)d_out;

    __nv_bfloat16 *hs_h,*hs_l,*wqk_h,*wqk_l,*wv_h,*wv_l,*wo_h,*wo_l;
    __nv_bfloat16 *qk_h,*qk_l,*v_h,*v_l,*y_h,*y_l;
    cudaGetSymbolAddress((void**)&hs_h, g_hs_h);   cudaGetSymbolAddress((void**)&hs_l, g_hs_l);
    cudaGetSymbolAddress((void**)&wqk_h, g_Wqk_h); cudaGetSymbolAddress((void**)&wqk_l, g_Wqk_l);
    cudaGetSymbolAddress((void**)&wv_h, g_Wv_h);   cudaGetSymbolAddress((void**)&wv_l, g_Wv_l);
    cudaGetSymbolAddress((void**)&wo_h, g_Wo_h);   cudaGetSymbolAddress((void**)&wo_l, g_Wo_l);
    cudaGetSymbolAddress((void**)&qk_h, g_qk_h);   cudaGetSymbolAddress((void**)&qk_l, g_qk_l);
    cudaGetSymbolAddress((void**)&v_h, g_v_h);     cudaGetSymbolAddress((void**)&v_l, g_v_l);
    cudaGetSymbolAddress((void**)&y_h, g_y_h);     cudaGetSymbolAddress((void**)&y_l, g_y_l);

    cudaFuncSetAttribute(attn_mma_kernel,
                         cudaFuncAttributeMaxDynamicSharedMemorySize, ATTN_SMEM);
    cudaFuncSetAttribute(gemm_pre_kernel,
                         cudaFuncAttributeMaxDynamicSharedMemorySize, GEMM_SMEM);

    // pre-split inputs
    const int n4_hs = MTOK*CCH/4, n4_w = CCH*CCH/4;
    split_kernel<<<(n4_hs+255)/256, 256>>>((const float4*)hs,
        (__nv_bfloat162*)hs_h, (__nv_bfloat162*)hs_l, n4_hs);
    split_kernel<<<(n4_w+255)/256, 256>>>((const float4*)Wqk,
        (__nv_bfloat162*)wqk_h, (__nv_bfloat162*)wqk_l, n4_w);
    split_kernel<<<(n4_w+255)/256, 256>>>((const float4*)Wv,
        (__nv_bfloat162*)wv_h, (__nv_bfloat162*)wv_l, n4_w);
    split_kernel<<<(n4_w+255)/256, 256>>>((const float4*)Wo,
        (__nv_bfloat162*)wo_h, (__nv_bfloat162*)wo_l, n4_w);

    dim3 ggrid(CCH/128, MTOK/128);   // (8, 32)
    gemm_pre_kernel<<<ggrid, 256, GEMM_SMEM>>>(hs_h, hs_l, wqk_h, wqk_l,
        bqk, nullptr, qk_h, qk_l);
    gemm_pre_kernel<<<ggrid, 256, GEMM_SMEM>>>(hs_h, hs_l, wv_h, wv_l,
        bv, nullptr, v_h, v_l);

    attn_mma_kernel<<<dim3(TT/64, BB*HH), 128, ATTN_SMEM>>>(qk_h, qk_l,
        v_h, v_l, y_h, y_l);

    gemm_pre_kernel<<<ggrid, 256, GEMM_SMEM>>>(y_h, y_l, wo_h, wo_l,
        bo, out, nullptr, nullptr);
}